// round 12
// baseline (speedup 1.0000x reference)
#include <cuda_runtime.h>
#include <cuda_fp16.h>
#include <cstdint>

// Problem constants
#define BB   64
#define NN   100
#define DD   32
#define E0   96
#define E1   160
#define E2   192
#define NODES (BB*NN)          // 6400
#define ROWS  (BB*NN*NN)       // 640000
#define TIL   64
#define NTILES (ROWS/TIL)      // 10000
#define GRID_E 304

// ---------------- scratch ----------------
__device__ __align__(16) float    g_u[NODES*E0];
__device__ __align__(16) float    g_v[NODES*E0];
__device__ __align__(16) float    g_agg[NODES*E2];
__device__ __align__(16) uint32_t g_w1h[6*20*64];    // 7680
__device__ __align__(16) uint32_t g_w2h[10*24*64];   // 15360
__device__ __align__(16) uint32_t g_nw0h[14*32*64];  // 28672
__device__ __align__(16) uint32_t g_nw1h[16*32*64];  // 32768
__device__ __align__(16) uint32_t g_nw2h[16*4*64];   // 4096

__device__ __forceinline__ float lrelu(float x){ return x > 0.f ? x : 0.2f*x; }

__device__ __forceinline__ uint32_t h2pack(float a, float b){
    __half2 h = __floats2half2_rn(a, b);
    return *(uint32_t*)&h;
}

// ---------------- cp.async ----------------
#define CP_ASYNC16(smem_u32, gptr) \
    asm volatile("cp.async.cg.shared.global [%0], [%1], 16;" :: "r"((uint32_t)(smem_u32)), "l"(gptr) : "memory")
#define CP_COMMIT() asm volatile("cp.async.commit_group;" ::: "memory")
#define CP_WAIT0()  asm volatile("cp.async.wait_group 0;" ::: "memory")

__device__ __forceinline__ uint32_t smem_to_u32(const void* p){
    uint32_t a;
    asm("{ .reg .u64 t; cvta.to.shared.u64 t, %1; cvt.u32.u64 %0, t; }" : "=r"(a) : "l"(p));
    return a;
}

// ---------------- mma.sync m16n8k16 fp16 (fp32 accum) ----------------
__device__ __forceinline__ void mma16(float c[4], const uint32_t a[4], const uint32_t b[2]){
    asm volatile("mma.sync.aligned.m16n8k16.row.col.f32.f16.f16.f32 "
        "{%0,%1,%2,%3}, {%4,%5,%6,%7}, {%8,%9}, {%0,%1,%2,%3};"
        : "+f"(c[0]), "+f"(c[1]), "+f"(c[2]), "+f"(c[3])
        : "r"(a[0]), "r"(a[1]), "r"(a[2]), "r"(a[3]), "r"(b[0]), "r"(b[1]));
}

__device__ __forceinline__ void ldsm4(uint32_t r[4], uint32_t addr){
    asm volatile("ldmatrix.sync.aligned.m8n8.x4.shared.b16 {%0,%1,%2,%3}, [%4];"
        : "=r"(r[0]), "=r"(r[1]), "=r"(r[2]), "=r"(r[3]) : "r"(addr));
}

__device__ __forceinline__ float redg(float v){
    v += __shfl_xor_sync(0xFFFFFFFFu, v, 4);
    v += __shfl_xor_sync(0xFFFFFFFFu, v, 8);
    v += __shfl_xor_sync(0xFFFFFFFFu, v, 16);
    return v;
}

// ---------------------------------------------------------------------------
// prep: fused w_prep (blocks 0..345) + node_pre (blocks 346..6745)
// ---------------------------------------------------------------------------
__device__ __forceinline__ void packW(uint32_t* dst, const float* W, int N, int NT, int idx){
    const int ks  = idx / (NT*64);
    const int rem = idx - ks*(NT*64);
    const int nt  = rem >> 6;
    const int l2  = rem & 63;
    const int lane = l2 >> 1, r = l2 & 1;
    const int gg = lane >> 2, tg = lane & 3;
    const int k0 = ks*16 + 2*tg + 8*r;
    const int n  = nt*8 + gg;
    dst[idx] = h2pack(W[k0*N + n], W[(k0+1)*N + n]);
}

#define WPREP_BLOCKS 346   // 346*256 = 88576 exactly

__global__ void prep(const float* __restrict__ x,
                     const float* __restrict__ w0, const float* __restrict__ b0,
                     const float* __restrict__ w1, const float* __restrict__ w2,
                     const float* __restrict__ nw0, const float* __restrict__ nw1,
                     const float* __restrict__ nw2)
{
    const int t = threadIdx.x;
    if (blockIdx.x < WPREP_BLOCKS) {
        const int idx = blockIdx.x * 256 + t;
        if      (idx < 7680)        packW(g_w1h,  w1,  E1,  20, idx);
        else if (idx < 23040)       packW(g_w2h,  w2,  E2,  24, idx - 7680);
        else if (idx < 51712)       packW(g_nw0h, nw0, 256, 32, idx - 23040);
        else if (idx < 84480)       packW(g_nw1h, nw1, 256, 32, idx - 51712);
        else                        packW(g_nw2h, nw2, 32,  4,  idx - 84480);
        return;
    }
    __shared__ float sx[DD];
    const int node = blockIdx.x - WPREP_BLOCKS;
    if (t < E2) g_agg[node*E2 + t] = 0.f;
    if (t < DD) sx[t] = x[node*DD + t];
    __syncthreads();
    if (t < E2) {
        float acc = 0.f;
        if (t < E0) {
            const int c = t;
            #pragma unroll
            for (int k = 0; k < DD; k++) acc += sx[k] * w0[k*E0 + c];
            g_u[node*E0 + c] = acc + b0[c];
        } else {
            const int c = t - E0;
            #pragma unroll
            for (int k = 0; k < DD; k++) acc += sx[k] * w0[(DD+k)*E0 + c];
            g_v[node*E0 + c] = acc;
        }
    }
}

// ---------------------------------------------------------------------------
// edge_kernel: persistent, fp16 mma + ldmatrix, weights smem-resident.
// grid=304, block=256 (8 warps = 2m x 4n), 2 CTAs/SM.  (R7 config)
// Reduce ends with direct per-warp atomics (no sPart stage): 4 barriers/tile.
// smem words: region [0,5376): H0 (stride 52w) / H1 (stride 84w, aliases)
//             sW1 @5376 (7680w) | sW2 @13056 (15360w) = 28416 w = 113664 B
// ---------------------------------------------------------------------------
#define H0S 52
#define H1S 84
#define SW1W 5376
#define SW2W 13056
#define EDGE_WORDS 28416
#define EDGE_SMEM_BYTES (EDGE_WORDS*4)

__global__ __launch_bounds__(256, 2)
void edge_kernel(const float* __restrict__ b1v, const float* __restrict__ b2v)
{
    extern __shared__ uint32_t smem_u[];
    uint32_t* region = smem_u;
    uint32_t* sW1 = smem_u + SW1W;
    uint32_t* sW2 = smem_u + SW2W;

    const int tid  = threadIdx.x;
    const int warp = tid >> 5;
    const int lane = tid & 31;
    const int g    = lane >> 2;
    const int tg   = lane & 3;
    const int wm   = warp >> 2;             // 0..1
    const int wn   = warp & 3;              // 0..3

    const int lrow = lane & 15;
    const int lcol = (lane >> 4) * 4;
    const uint32_t regB = smem_to_u32(region);
    const uint32_t a0H0 = regB + (((wm*32 +  0 + lrow)*H0S) + lcol)*4;
    const uint32_t a1H0 = regB + (((wm*32 + 16 + lrow)*H0S) + lcol)*4;
    const uint32_t a0H1 = regB + (((wm*32 +  0 + lrow)*H1S) + lcol)*4;
    const uint32_t a1H1 = regB + (((wm*32 + 16 + lrow)*H1S) + lcol)*4;

    // hoist tile-invariant biases into registers
    float bb1[5][2], bb2[6][2];
    #pragma unroll
    for (int nt = 0; nt < 5; nt++) {
        const int col = wn*40 + nt*8 + 2*tg;
        bb1[nt][0] = __ldg(b1v + col);
        bb1[nt][1] = __ldg(b1v + col + 1);
    }
    #pragma unroll
    for (int nt = 0; nt < 6; nt++) {
        const int col = wn*48 + nt*8 + 2*tg;
        bb2[nt][0] = __ldg(b2v + col);
        bb2[nt][1] = __ldg(b2v + col + 1);
    }

    // ---- preload weights once ----
    {
        const uint32_t s1 = smem_to_u32(sW1);
        for (int i = tid; i < 1920; i += 256) CP_ASYNC16(s1 + i*16, (const void*)(g_w1h + i*4));
        const uint32_t s2 = smem_to_u32(sW2);
        for (int i = tid; i < 3840; i += 256) CP_ASYNC16(s2 + i*16, (const void*)(g_w2h + i*4));
        CP_COMMIT();
        CP_WAIT0();
    }
    __syncthreads();

    for (int tile = blockIdx.x; tile < NTILES; tile += GRID_E) {
        const int base = tile * TIL;

        // ---- build H0 = fp16(lrelu(u_i + v_j)) -> region [row][52w] ----
        {
            const int row = tid >> 2;
            const int kq  = tid & 3;
            const int R   = base + row;
            const int nu  = R / 100;
            const int nv  = (R / 10000) * 100 + (R - nu*100);
            const float4* up = (const float4*)(g_u + nu*E0) + kq*6;
            const float4* vp = (const float4*)(g_v + nv*E0) + kq*6;
            uint32_t* dst = region + row*H0S + kq*12;
            #pragma unroll
            for (int i = 0; i < 6; i++) {
                const float4 uu = up[i];
                const float4 vv = vp[i];
                uint2 w;
                w.x = h2pack(lrelu(uu.x + vv.x), lrelu(uu.y + vv.y));
                w.y = h2pack(lrelu(uu.z + vv.z), lrelu(uu.w + vv.w));
                *(uint2*)(dst + i*2) = w;
            }
        }
        __syncthreads();                               // (1) H0 ready

        // ---- GEMM1: C1[64x160] = H0[64x96] @ W1 ----
        float c1[2][5][4];
        #pragma unroll
        for (int mt = 0; mt < 2; mt++)
            #pragma unroll
            for (int nt = 0; nt < 5; nt++)
                #pragma unroll
                for (int e = 0; e < 4; e++) c1[mt][nt][e] = 0.f;

        #pragma unroll
        for (int ks = 0; ks < 6; ks++) {
            uint32_t a0[4], a1[4];
            ldsm4(a0, a0H0 + ks*32);
            ldsm4(a1, a1H0 + ks*32);
            #pragma unroll
            for (int nt = 0; nt < 5; nt++) {
                uint32_t b[2];
                *(uint2*)b = *(const uint2*)&sW1[((ks*20 + wn*5 + nt)*32 + lane)*2];
                mma16(c1[0][nt], a0, b);
                mma16(c1[1][nt], a1, b);
            }
        }
        __syncthreads();                               // (2) H0 dead

        // ---- epilogue1: H1 = fp16(lrelu(C1 + b1)) -> region [row][84w] ----
        #pragma unroll
        for (int nt = 0; nt < 5; nt++) {
            const int col = wn*40 + nt*8 + 2*tg;
            #pragma unroll
            for (int mt = 0; mt < 2; mt++) {
                const int r0 = wm*32 + mt*16 + g;
                region[r0*H1S + (col>>1)]     = h2pack(lrelu(c1[mt][nt][0] + bb1[nt][0]), lrelu(c1[mt][nt][1] + bb1[nt][1]));
                region[(r0+8)*H1S + (col>>1)] = h2pack(lrelu(c1[mt][nt][2] + bb1[nt][0]), lrelu(c1[mt][nt][3] + bb1[nt][1]));
            }
        }
        __syncthreads();                               // (3) H1 ready

        // ---- GEMM2: C2[64x192] = H1[64x160] @ W2 ----
        float c2[2][6][4];
        #pragma unroll
        for (int mt = 0; mt < 2; mt++)
            #pragma unroll
            for (int nt = 0; nt < 6; nt++)
                #pragma unroll
                for (int e = 0; e < 4; e++) c2[mt][nt][e] = 0.f;

        #pragma unroll
        for (int ks = 0; ks < 10; ks++) {
            uint32_t a0[4], a1[4];
            ldsm4(a0, a0H1 + ks*32);
            ldsm4(a1, a1H1 + ks*32);
            #pragma unroll
            for (int nt = 0; nt < 6; nt++) {
                uint32_t b[2];
                *(uint2*)b = *(const uint2*)&sW2[((ks*24 + wn*6 + nt)*32 + lane)*2];
                mma16(c2[0][nt], a0, b);
                mma16(c2[1][nt], a1, b);
            }
        }

        // ---- in-register segmented reduce (each warp's 32 rows span <=2 segs)
        //      then DIRECT per-warp atomics (no sPart stage) ----
        const int s0  = base / 100;
        const int l0w = (base + wm*32)/100 - s0;           // 0 or 1
        const int r1w = (s0 + l0w + 1)*100 - base;         // boundary row

        float acc[2][12];
        #pragma unroll
        for (int s = 0; s < 2; s++)
            #pragma unroll
            for (int i = 0; i < 12; i++) acc[s][i] = 0.f;

        #pragma unroll
        for (int nt = 0; nt < 6; nt++) {
            #pragma unroll
            for (int mt = 0; mt < 2; mt++) {
                const int offA = wm*32 + mt*16 + g;
                const int offB = offA + 8;
                const int sA = (offA >= r1w);
                const int sB = (offB >= r1w);
                acc[sA][nt*2  ] += lrelu(c2[mt][nt][0] + bb2[nt][0]);
                acc[sA][nt*2+1] += lrelu(c2[mt][nt][1] + bb2[nt][1]);
                acc[sB][nt*2  ] += lrelu(c2[mt][nt][2] + bb2[nt][0]);
                acc[sB][nt*2+1] += lrelu(c2[mt][nt][3] + bb2[nt][1]);
            }
        }
        const bool two = (r1w < wm*32 + 32);
        #pragma unroll
        for (int i = 0; i < 12; i++) {
            acc[0][i] = redg(acc[0][i]);
            if (two) acc[1][i] = redg(acc[1][i]);
        }
        if (lane < 4) {
            const int segA = s0 + l0w;
            #pragma unroll
            for (int nt = 0; nt < 6; nt++) {
                const int col = wn*48 + nt*8 + 2*lane;
                atomicAdd(&g_agg[segA*E2 + col],     acc[0][nt*2]);
                atomicAdd(&g_agg[segA*E2 + col + 1], acc[0][nt*2+1]);
                if (two) {
                    atomicAdd(&g_agg[(segA+1)*E2 + col],     acc[1][nt*2]);
                    atomicAdd(&g_agg[(segA+1)*E2 + col + 1], acc[1][nt*2+1]);
                }
            }
        }
        __syncthreads();                               // (4) H1 reads done before next build
    }
}

// ---------------------------------------------------------------------------
// node_mlp: fp16 mma + ldmatrix, 32 rows/CTA (two 16-row halves), grid=200,
// block=256. smem: bufA [32][132w] + bufB [32][132w]
// ---------------------------------------------------------------------------
#define NBS 132
#define NODE_SMEM_BYTES (2*32*NBS*4)

__global__ __launch_bounds__(256)
void node_mlp(const float* __restrict__ x,
              const float* __restrict__ b0,
              const float* __restrict__ b1,
              const float* __restrict__ b2,
              float* __restrict__ out)
{
    extern __shared__ uint32_t smem_u[];
    uint32_t* bufA = smem_u;
    uint32_t* bufB = smem_u + 32*NBS;

    const int tid  = threadIdx.x;
    const int warp = tid >> 5;
    const int lane = tid & 31;
    const int g    = lane >> 2;
    const int tg   = lane & 3;
    const int half = warp >> 2;
    const int wq   = warp & 3;
    const int base = blockIdx.x * 32;

    const int lrow = lane & 15;
    const int lcol = (lane >> 4) * 4;
    const uint32_t aA = smem_to_u32(bufA) + ((half*16 + lrow)*NBS + lcol)*4;
    const uint32_t aB = smem_to_u32(bufB) + ((half*16 + lrow)*NBS + lcol)*4;

    for (int i = tid; i < 32*112; i += 256) {
        const int row = i / 112;
        const int kw  = i - row*112;
        const int k   = kw*2;
        const int node = base + row;
        float v0, v1;
        if (k < E2) { v0 = g_agg[node*E2 + k]; v1 = g_agg[node*E2 + k + 1]; }
        else        { v0 = x[node*DD + (k - E2)]; v1 = x[node*DD + (k - E2) + 1]; }
        bufA[row*NBS + kw] = h2pack(v0, v1);
    }
    __syncthreads();

    for (int layer = 0; layer < 2; layer++) {
        const uint32_t aIn  = layer ? aB : aA;
        uint32_t* sOut      = layer ? bufA : bufB;
        const uint32_t* wpk = layer ? g_nw1h : g_nw0h;
        const float* bias   = layer ? b1 : b0;
        const int nks       = layer ? 16 : 14;

        float c[8][4];
        #pragma unroll
        for (int nt = 0; nt < 8; nt++)
            #pragma unroll
            for (int e = 0; e < 4; e++) c[nt][e] = 0.f;

        for (int ks = 0; ks < nks; ks++) {
            uint32_t a[4];
            ldsm4(a, aIn + ks*32);
            #pragma unroll
            for (int nt = 0; nt < 8; nt++) {
                uint32_t b[2];
                *(uint2*)b = *(const uint2*)&wpk[((ks*32 + wq*8 + nt)*32 + lane)*2];
                mma16(c[nt], a, b);
            }
        }
        __syncthreads();
        #pragma unroll
        for (int nt = 0; nt < 8; nt++) {
            const int col = wq*64 + nt*8 + 2*tg;
            const float ba = __ldg(bias + col);
            const float bb = __ldg(bias + col + 1);
            const int r0 = half*16 + g;
            sOut[r0*NBS + (col>>1)]     = h2pack(lrelu(c[nt][0] + ba), lrelu(c[nt][1] + bb));
            sOut[(r0+8)*NBS + (col>>1)] = h2pack(lrelu(c[nt][2] + ba), lrelu(c[nt][3] + bb));
        }
        __syncthreads();
    }

    {
        float c3[4] = {0.f, 0.f, 0.f, 0.f};
        for (int ks = 0; ks < 16; ks++) {
            uint32_t a[4];
            ldsm4(a, aA + ks*32);
            uint32_t b[2];
            *(uint2*)b = *(const uint2*)&g_nw2h[((ks*4 + wq)*32 + lane)*2];
            mma16(c3, a, b);
        }
        const int col = wq*8 + 2*tg;
        const float ba = __ldg(b2 + col);
        const float bb = __ldg(b2 + col + 1);
        float2 lo = {c3[0] + ba, c3[1] + bb};
        float2 hi = {c3[2] + ba, c3[3] + bb};
        const int r0 = base + half*16 + g;
        *(float2*)&out[r0*32 + col]       = lo;
        *(float2*)&out[(r0 + 8)*32 + col] = hi;
    }
}

// ---------------------------------------------------------------------------
extern "C" void kernel_launch(void* const* d_in, const int* in_sizes, int n_in,
                              void* d_out, int out_size)
{
    const float* x     = (const float*)d_in[0];
    const float* fe_w0 = (const float*)d_in[1];
    const float* fe_b0 = (const float*)d_in[2];
    const float* fe_w1 = (const float*)d_in[3];
    const float* fe_b1 = (const float*)d_in[4];
    const float* fe_w2 = (const float*)d_in[5];
    const float* fe_b2 = (const float*)d_in[6];
    const float* fn_w0 = (const float*)d_in[7];
    const float* fn_b0 = (const float*)d_in[8];
    const float* fn_w1 = (const float*)d_in[9];
    const float* fn_b1 = (const float*)d_in[10];
    const float* fn_w2 = (const float*)d_in[11];
    const float* fn_b2 = (const float*)d_in[12];
    float* out = (float*)d_out;

    cudaFuncSetAttribute(edge_kernel, cudaFuncAttributeMaxDynamicSharedMemorySize, EDGE_SMEM_BYTES);
    cudaFuncSetAttribute(node_mlp,    cudaFuncAttributeMaxDynamicSharedMemorySize, NODE_SMEM_BYTES);

    prep<<<WPREP_BLOCKS + NODES, 256>>>(x, fe_w0, fe_b0, fe_w1, fe_w2, fn_w0, fn_w1, fn_w2);
    edge_kernel<<<GRID_E, 256, EDGE_SMEM_BYTES>>>(fe_b1, fe_b2);
    node_mlp<<<NODES/32, 256, NODE_SMEM_BYTES>>>(x, fn_b0, fn_b1, fn_b2, out);
}

// round 13
// speedup vs baseline: 1.2655x; 1.2655x over previous
#include <cuda_runtime.h>
#include <cuda_fp16.h>
#include <cstdint>

// Problem constants
#define BB   64
#define NN   100
#define DD   32
#define E0   96
#define E1   160
#define E2   192
#define NODES (BB*NN)          // 6400
#define ROWS  (BB*NN*NN)       // 640000
#define TIL   64
#define NTILES (ROWS/TIL)      // 10000
#define GRID_E 304

// ---------------- scratch ----------------
__device__ __align__(16) float    g_u[NODES*E0];
__device__ __align__(16) float    g_v[NODES*E0];
__device__ __align__(16) float    g_agg[NODES*E2];
__device__ __align__(16) uint32_t g_w1h[6*20*64];    // 7680
__device__ __align__(16) uint32_t g_w2h[10*24*64];   // 15360
__device__ __align__(16) uint32_t g_nw0h[14*32*64];  // 28672
__device__ __align__(16) uint32_t g_nw1h[16*32*64];  // 32768
__device__ __align__(16) uint32_t g_nw2h[16*4*64];   // 4096

__device__ __forceinline__ float lrelu(float x){ return x > 0.f ? x : 0.2f*x; }

__device__ __forceinline__ uint32_t h2pack(float a, float b){
    __half2 h = __floats2half2_rn(a, b);
    return *(uint32_t*)&h;
}

// ---------------- cp.async ----------------
#define CP_ASYNC16(smem_u32, gptr) \
    asm volatile("cp.async.cg.shared.global [%0], [%1], 16;" :: "r"((uint32_t)(smem_u32)), "l"(gptr) : "memory")
#define CP_COMMIT() asm volatile("cp.async.commit_group;" ::: "memory")
#define CP_WAIT0()  asm volatile("cp.async.wait_group 0;" ::: "memory")

__device__ __forceinline__ uint32_t smem_to_u32(const void* p){
    uint32_t a;
    asm("{ .reg .u64 t; cvta.to.shared.u64 t, %1; cvt.u32.u64 %0, t; }" : "=r"(a) : "l"(p));
    return a;
}

// ---------------- mma.sync m16n8k16 fp16 (fp32 accum) ----------------
__device__ __forceinline__ void mma16(float c[4], const uint32_t a[4], const uint32_t b[2]){
    asm volatile("mma.sync.aligned.m16n8k16.row.col.f32.f16.f16.f32 "
        "{%0,%1,%2,%3}, {%4,%5,%6,%7}, {%8,%9}, {%0,%1,%2,%3};"
        : "+f"(c[0]), "+f"(c[1]), "+f"(c[2]), "+f"(c[3])
        : "r"(a[0]), "r"(a[1]), "r"(a[2]), "r"(a[3]), "r"(b[0]), "r"(b[1]));
}

__device__ __forceinline__ void ldsm4(uint32_t r[4], uint32_t addr){
    asm volatile("ldmatrix.sync.aligned.m8n8.x4.shared.b16 {%0,%1,%2,%3}, [%4];"
        : "=r"(r[0]), "=r"(r[1]), "=r"(r[2]), "=r"(r[3]) : "r"(addr));
}

// ---------------------------------------------------------------------------
// prep: fused w_prep (blocks 0..345) + node_pre (blocks 346..6745)
// ---------------------------------------------------------------------------
__device__ __forceinline__ void packW(uint32_t* dst, const float* W, int N, int NT, int idx){
    const int ks  = idx / (NT*64);
    const int rem = idx - ks*(NT*64);
    const int nt  = rem >> 6;
    const int l2  = rem & 63;
    const int lane = l2 >> 1, r = l2 & 1;
    const int gg = lane >> 2, tg = lane & 3;
    const int k0 = ks*16 + 2*tg + 8*r;
    const int n  = nt*8 + gg;
    dst[idx] = h2pack(W[k0*N + n], W[(k0+1)*N + n]);
}

#define WPREP_BLOCKS 346   // 346*256 = 88576 exactly

__global__ void prep(const float* __restrict__ x,
                     const float* __restrict__ w0, const float* __restrict__ b0,
                     const float* __restrict__ w1, const float* __restrict__ w2,
                     const float* __restrict__ nw0, const float* __restrict__ nw1,
                     const float* __restrict__ nw2)
{
    const int t = threadIdx.x;
    if (blockIdx.x < WPREP_BLOCKS) {
        const int idx = blockIdx.x * 256 + t;
        if      (idx < 7680)        packW(g_w1h,  w1,  E1,  20, idx);
        else if (idx < 23040)       packW(g_w2h,  w2,  E2,  24, idx - 7680);
        else if (idx < 51712)       packW(g_nw0h, nw0, 256, 32, idx - 23040);
        else if (idx < 84480)       packW(g_nw1h, nw1, 256, 32, idx - 51712);
        else                        packW(g_nw2h, nw2, 32,  4,  idx - 84480);
        return;
    }
    __shared__ float sx[DD];
    const int node = blockIdx.x - WPREP_BLOCKS;
    if (t < E2) g_agg[node*E2 + t] = 0.f;
    if (t < DD) sx[t] = x[node*DD + t];
    __syncthreads();
    if (t < E2) {
        float acc = 0.f;
        if (t < E0) {
            const int c = t;
            #pragma unroll
            for (int k = 0; k < DD; k++) acc += sx[k] * w0[k*E0 + c];
            g_u[node*E0 + c] = acc + b0[c];
        } else {
            const int c = t - E0;
            #pragma unroll
            for (int k = 0; k < DD; k++) acc += sx[k] * w0[(DD+k)*E0 + c];
            g_v[node*E0 + c] = acc;
        }
    }
}

// ---------------------------------------------------------------------------
// edge_kernel: persistent, fp16 mma + ldmatrix, weights smem-resident.
// grid=304, block=256 (8 warps = 2m x 4n), smem = 28416 words = 113664 B
// region [0,5376): H0 (stride 52w) / H1 (stride 84w); sPart @4608 (768w)
// sW1 @5376 (7680w) | sW2 @13056 (15360w)
// (R7 champion config + L1 prefetch of next tile's u/v before GEMM2)
// ---------------------------------------------------------------------------
#define H0S 52
#define H1S 84
#define SPARTW 4608
#define SW1W 5376
#define SW2W 13056
#define EDGE_WORDS 28416
#define EDGE_SMEM_BYTES (EDGE_WORDS*4)

__global__ __launch_bounds__(256, 2)
void edge_kernel(const float* __restrict__ b1v, const float* __restrict__ b2v)
{
    extern __shared__ uint32_t smem_u[];
    uint32_t* region = smem_u;
    uint32_t* sW1 = smem_u + SW1W;
    uint32_t* sW2 = smem_u + SW2W;
    float*    sPart = (float*)(smem_u + SPARTW);   // [wm*2+seg][192]

    const int tid  = threadIdx.x;
    const int warp = tid >> 5;
    const int lane = tid & 31;
    const int g    = lane >> 2;
    const int tg   = lane & 3;
    const int wm   = warp >> 2;             // 0..1
    const int wn   = warp & 3;              // 0..3

    // ldmatrix per-lane address components
    const int lrow = lane & 15;
    const int lcol = (lane >> 4) * 4;
    const uint32_t regB = smem_to_u32(region);
    uint32_t a0H0 = regB + (((wm*32 +  0 + lrow)*H0S) + lcol)*4;
    uint32_t a1H0 = regB + (((wm*32 + 16 + lrow)*H0S) + lcol)*4;
    uint32_t a0H1 = regB + (((wm*32 +  0 + lrow)*H1S) + lcol)*4;
    uint32_t a1H1 = regB + (((wm*32 + 16 + lrow)*H1S) + lcol)*4;

    // hoist tile-invariant biases into registers
    float bb1[5][2], bb2[6][2];
    #pragma unroll
    for (int nt = 0; nt < 5; nt++) {
        const int col = wn*40 + nt*8 + 2*tg;
        bb1[nt][0] = __ldg(b1v + col);
        bb1[nt][1] = __ldg(b1v + col + 1);
    }
    #pragma unroll
    for (int nt = 0; nt < 6; nt++) {
        const int col = wn*48 + nt*8 + 2*tg;
        bb2[nt][0] = __ldg(b2v + col);
        bb2[nt][1] = __ldg(b2v + col + 1);
    }

    // ---- preload weights once ----
    {
        const uint32_t s1 = smem_to_u32(sW1);
        for (int i = tid; i < 1920; i += 256) CP_ASYNC16(s1 + i*16, (const void*)(g_w1h + i*4));
        const uint32_t s2 = smem_to_u32(sW2);
        for (int i = tid; i < 3840; i += 256) CP_ASYNC16(s2 + i*16, (const void*)(g_w2h + i*4));
        CP_COMMIT();
        CP_WAIT0();
    }
    __syncthreads();

    for (int tile = blockIdx.x; tile < NTILES; tile += GRID_E) {
        const int base = tile * TIL;

        // ---- build H0 = fp16(lrelu(u_i + v_j)) -> region [row][52w] ----
        {
            const int row = tid >> 2;
            const int kq  = tid & 3;
            const int R   = base + row;
            const int nu  = R / 100;
            const int nv  = (R / 10000) * 100 + (R - nu*100);
            const float4* up = (const float4*)(g_u + nu*E0) + kq*6;
            const float4* vp = (const float4*)(g_v + nv*E0) + kq*6;
            uint32_t* dst = region + row*H0S + kq*12;
            #pragma unroll
            for (int i = 0; i < 6; i++) {
                const float4 uu = up[i];
                const float4 vv = vp[i];
                uint2 w;
                w.x = h2pack(lrelu(uu.x + vv.x), lrelu(uu.y + vv.y));
                w.y = h2pack(lrelu(uu.z + vv.z), lrelu(uu.w + vv.w));
                *(uint2*)(dst + i*2) = w;
            }
        }
        __syncthreads();                               // (C)

        // ---- GEMM1: C1[64x160] = H0[64x96] @ W1 ----
        float c1[2][5][4];
        #pragma unroll
        for (int mt = 0; mt < 2; mt++)
            #pragma unroll
            for (int nt = 0; nt < 5; nt++)
                #pragma unroll
                for (int e = 0; e < 4; e++) c1[mt][nt][e] = 0.f;

        #pragma unroll
        for (int ks = 0; ks < 6; ks++) {
            uint32_t a0[4], a1[4];
            ldsm4(a0, a0H0 + ks*32);
            ldsm4(a1, a1H0 + ks*32);
            #pragma unroll
            for (int nt = 0; nt < 5; nt++) {
                uint32_t b[2];
                *(uint2*)b = *(const uint2*)&sW1[((ks*20 + wn*5 + nt)*32 + lane)*2];
                mma16(c1[0][nt], a0, b);
                mma16(c1[1][nt], a1, b);
            }
        }
        __syncthreads();                               // (D) H0 dead

        // ---- epilogue1: H1 = fp16(lrelu(C1 + b1)) -> region [row][84w] ----
        #pragma unroll
        for (int nt = 0; nt < 5; nt++) {
            const int col = wn*40 + nt*8 + 2*tg;
            #pragma unroll
            for (int mt = 0; mt < 2; mt++) {
                const int r0 = wm*32 + mt*16 + g;
                region[r0*H1S + (col>>1)]     = h2pack(lrelu(c1[mt][nt][0] + bb1[nt][0]), lrelu(c1[mt][nt][1] + bb1[nt][1]));
                region[(r0+8)*H1S + (col>>1)] = h2pack(lrelu(c1[mt][nt][2] + bb1[nt][0]), lrelu(c1[mt][nt][3] + bb1[nt][1]));
            }
        }
        __syncthreads();                               // (E)

        // ---- prefetch next tile's u/v into L1 (overlaps GEMM2) ----
        {
            const int ntile = tile + GRID_E;
            if (ntile < NTILES) {
                const int row = tid >> 2;
                const int kq  = tid & 3;
                const int R   = ntile*TIL + row;
                const int nu  = R / 100;
                const int nv  = (R / 10000) * 100 + (R - nu*100);
                const char* up = (const char*)((const float4*)(g_u + nu*E0) + kq*6);
                const char* vp = (const char*)((const float4*)(g_v + nv*E0) + kq*6);
                asm volatile("prefetch.global.L1 [%0];" :: "l"(up));
                asm volatile("prefetch.global.L1 [%0];" :: "l"(vp));
                asm volatile("prefetch.global.L1 [%0];" :: "l"(up + 64));
                asm volatile("prefetch.global.L1 [%0];" :: "l"(vp + 64));
            }
        }

        // ---- GEMM2: C2[64x192] = H1[64x160] @ W2 ----
        float c2[2][6][4];
        #pragma unroll
        for (int mt = 0; mt < 2; mt++)
            #pragma unroll
            for (int nt = 0; nt < 6; nt++)
                #pragma unroll
                for (int e = 0; e < 4; e++) c2[mt][nt][e] = 0.f;

        #pragma unroll
        for (int ks = 0; ks < 10; ks++) {
            uint32_t a0[4], a1[4];
            ldsm4(a0, a0H1 + ks*32);
            ldsm4(a1, a1H1 + ks*32);
            #pragma unroll
            for (int nt = 0; nt < 6; nt++) {
                uint32_t b[2];
                *(uint2*)b = *(const uint2*)&sW2[((ks*24 + wn*6 + nt)*32 + lane)*2];
                mma16(c2[0][nt], a0, b);
                mma16(c2[1][nt], a1, b);
            }
        }

        // ---- in-register segmented reduce (<=2 segments/tile) ----
        const int s0 = base / 100;
        int r1 = (s0 + 1)*100 - base;  if (r1 > TIL) r1 = TIL;

        float acc[2][12];
        #pragma unroll
        for (int s = 0; s < 2; s++)
            #pragma unroll
            for (int i = 0; i < 12; i++) acc[s][i] = 0.f;

        #pragma unroll
        for (int nt = 0; nt < 6; nt++) {
            #pragma unroll
            for (int mt = 0; mt < 2; mt++) {
                const int offA = wm*32 + mt*16 + g;
                const int offB = offA + 8;
                const int sA = (offA >= r1);
                const int sB = (offB >= r1);
                acc[sA][nt*2  ] += lrelu(c2[mt][nt][0] + bb2[nt][0]);
                acc[sA][nt*2+1] += lrelu(c2[mt][nt][1] + bb2[nt][1]);
                acc[sB][nt*2  ] += lrelu(c2[mt][nt][2] + bb2[nt][0]);
                acc[sB][nt*2+1] += lrelu(c2[mt][nt][3] + bb2[nt][1]);
            }
        }
        #pragma unroll
        for (int off = 4; off < 32; off <<= 1)
            #pragma unroll
            for (int s = 0; s < 2; s++)
                #pragma unroll
                for (int i = 0; i < 12; i++)
                    acc[s][i] += __shfl_xor_sync(0xFFFFFFFFu, acc[s][i], off);

        __syncthreads();                               // (A)

        if (g == 0) {
            #pragma unroll
            for (int nt = 0; nt < 6; nt++) {
                const int col = wn*48 + nt*8 + 2*tg;
                sPart[(wm*2 + 0)*192 + col    ] = acc[0][nt*2];
                sPart[(wm*2 + 0)*192 + col + 1] = acc[0][nt*2+1];
                sPart[(wm*2 + 1)*192 + col    ] = acc[1][nt*2];
                sPart[(wm*2 + 1)*192 + col + 1] = acc[1][nt*2+1];
            }
        }
        __syncthreads();                               // (B)

        if (tid < 192) {
            const float v0 = sPart[tid] + sPart[384 + tid];
            atomicAdd(&g_agg[s0*E2 + tid], v0);
            if (r1 < TIL) {
                const float v1 = sPart[192 + tid] + sPart[576 + tid];
                atomicAdd(&g_agg[(s0 + 1)*E2 + tid], v1);
            }
        }
        // next build writes [0,3328) only; sPart [4608,5376) untouched
    }
}

// ---------------------------------------------------------------------------
// node_mlp: fp16 mma + ldmatrix, 32 rows/CTA (two 16-row halves), grid=200,
// block=256. smem: bufA [32][132w] + bufB [32][132w]
// ---------------------------------------------------------------------------
#define NBS 132
#define NODE_SMEM_BYTES (2*32*NBS*4)

__global__ __launch_bounds__(256)
void node_mlp(const float* __restrict__ x,
              const float* __restrict__ b0,
              const float* __restrict__ b1,
              const float* __restrict__ b2,
              float* __restrict__ out)
{
    extern __shared__ uint32_t smem_u[];
    uint32_t* bufA = smem_u;
    uint32_t* bufB = smem_u + 32*NBS;

    const int tid  = threadIdx.x;
    const int warp = tid >> 5;
    const int lane = tid & 31;
    const int g    = lane >> 2;
    const int tg   = lane & 3;
    const int half = warp >> 2;
    const int wq   = warp & 3;
    const int base = blockIdx.x * 32;

    const int lrow = lane & 15;
    const int lcol = (lane >> 4) * 4;
    const uint32_t aA = smem_to_u32(bufA) + ((half*16 + lrow)*NBS + lcol)*4;
    const uint32_t aB = smem_to_u32(bufB) + ((half*16 + lrow)*NBS + lcol)*4;

    for (int i = tid; i < 32*112; i += 256) {
        const int row = i / 112;
        const int kw  = i - row*112;
        const int k   = kw*2;
        const int node = base + row;
        float v0, v1;
        if (k < E2) { v0 = g_agg[node*E2 + k]; v1 = g_agg[node*E2 + k + 1]; }
        else        { v0 = x[node*DD + (k - E2)]; v1 = x[node*DD + (k - E2) + 1]; }
        bufA[row*NBS + kw] = h2pack(v0, v1);
    }
    __syncthreads();

    for (int layer = 0; layer < 2; layer++) {
        const uint32_t aIn  = layer ? aB : aA;
        uint32_t* sOut      = layer ? bufA : bufB;
        const uint32_t* wpk = layer ? g_nw1h : g_nw0h;
        const float* bias   = layer ? b1 : b0;
        const int nks       = layer ? 16 : 14;

        float c[8][4];
        #pragma unroll
        for (int nt = 0; nt < 8; nt++)
            #pragma unroll
            for (int e = 0; e < 4; e++) c[nt][e] = 0.f;

        for (int ks = 0; ks < nks; ks++) {
            uint32_t a[4];
            ldsm4(a, aIn + ks*32);
            #pragma unroll
            for (int nt = 0; nt < 8; nt++) {
                uint32_t b[2];
                *(uint2*)b = *(const uint2*)&wpk[((ks*32 + wq*8 + nt)*32 + lane)*2];
                mma16(c[nt], a, b);
            }
        }
        __syncthreads();
        #pragma unroll
        for (int nt = 0; nt < 8; nt++) {
            const int col = wq*64 + nt*8 + 2*tg;
            const float ba = __ldg(bias + col);
            const float bb = __ldg(bias + col + 1);
            const int r0 = half*16 + g;
            sOut[r0*NBS + (col>>1)]     = h2pack(lrelu(c[nt][0] + ba), lrelu(c[nt][1] + bb));
            sOut[(r0+8)*NBS + (col>>1)] = h2pack(lrelu(c[nt][2] + ba), lrelu(c[nt][3] + bb));
        }
        __syncthreads();
    }

    {
        float c3[4] = {0.f, 0.f, 0.f, 0.f};
        for (int ks = 0; ks < 16; ks++) {
            uint32_t a[4];
            ldsm4(a, aA + ks*32);
            uint32_t b[2];
            *(uint2*)b = *(const uint2*)&g_nw2h[((ks*4 + wq)*32 + lane)*2];
            mma16(c3, a, b);
        }
        const int col = wq*8 + 2*tg;
        const float ba = __ldg(b2 + col);
        const float bb = __ldg(b2 + col + 1);
        float2 lo = {c3[0] + ba, c3[1] + bb};
        float2 hi = {c3[2] + ba, c3[3] + bb};
        const int r0 = base + half*16 + g;
        *(float2*)&out[r0*32 + col]       = lo;
        *(float2*)&out[(r0 + 8)*32 + col] = hi;
    }
}

// ---------------------------------------------------------------------------
extern "C" void kernel_launch(void* const* d_in, const int* in_sizes, int n_in,
                              void* d_out, int out_size)
{
    const float* x     = (const float*)d_in[0];
    const float* fe_w0 = (const float*)d_in[1];
    const float* fe_b0 = (const float*)d_in[2];
    const float* fe_w1 = (const float*)d_in[3];
    const float* fe_b1 = (const float*)d_in[4];
    const float* fe_w2 = (const float*)d_in[5];
    const float* fe_b2 = (const float*)d_in[6];
    const float* fn_w0 = (const float*)d_in[7];
    const float* fn_b0 = (const float*)d_in[8];
    const float* fn_w1 = (const float*)d_in[9];
    const float* fn_b1 = (const float*)d_in[10];
    const float* fn_w2 = (const float*)d_in[11];
    const float* fn_b2 = (const float*)d_in[12];
    float* out = (float*)d_out;

    cudaFuncSetAttribute(edge_kernel, cudaFuncAttributeMaxDynamicSharedMemorySize, EDGE_SMEM_BYTES);
    cudaFuncSetAttribute(node_mlp,    cudaFuncAttributeMaxDynamicSharedMemorySize, NODE_SMEM_BYTES);

    prep<<<WPREP_BLOCKS + NODES, 256>>>(x, fe_w0, fe_b0, fe_w1, fe_w2, fn_w0, fn_w1, fn_w2);
    edge_kernel<<<GRID_E, 256, EDGE_SMEM_BYTES>>>(fe_b1, fe_b2);
    node_mlp<<<NODES/32, 256, NODE_SMEM_BYTES>>>(x, fn_b0, fn_b1, fn_b2, out);
}

// round 15
// speedup vs baseline: 1.3911x; 1.0992x over previous
#include <cuda_runtime.h>
#include <cuda_fp16.h>
#include <cstdint>

// Problem constants
#define BB   64
#define NN   100
#define DD   32
#define E0   96
#define E1   160
#define E2   192
#define NODES (BB*NN)          // 6400
#define ROWS  (BB*NN*NN)       // 640000
#define TIL   64
#define NTILES (ROWS/TIL)      // 10000
#define GRID_E 304

// ---------------- scratch ----------------
__device__ __align__(16) float    g_u[NODES*E0];
__device__ __align__(16) float    g_v[NODES*E0];
__device__ __align__(16) float    g_agg[NODES*E2];
__device__ __align__(16) uint32_t g_w1h[6*20*64];    // 7680
__device__ __align__(16) uint32_t g_w2h[10*24*64];   // 15360
__device__ __align__(16) uint32_t g_nw0h[14*32*64];  // 28672
__device__ __align__(16) uint32_t g_nw1h[16*32*64];  // 32768
__device__ __align__(16) uint32_t g_nw2h[16*4*64];   // 4096

__device__ __forceinline__ float lrelu(float x){ return x > 0.f ? x : 0.2f*x; }

__device__ __forceinline__ uint32_t h2pack(float a, float b){
    __half2 h = __floats2half2_rn(a, b);
    return *(uint32_t*)&h;
}

// ---------------- cp.async ----------------
#define CP_ASYNC16(smem_u32, gptr) \
    asm volatile("cp.async.cg.shared.global [%0], [%1], 16;" :: "r"((uint32_t)(smem_u32)), "l"(gptr) : "memory")
#define CP_COMMIT() asm volatile("cp.async.commit_group;" ::: "memory")
#define CP_WAIT0()  asm volatile("cp.async.wait_group 0;" ::: "memory")

__device__ __forceinline__ uint32_t smem_to_u32(const void* p){
    uint32_t a;
    asm("{ .reg .u64 t; cvta.to.shared.u64 t, %1; cvt.u32.u64 %0, t; }" : "=r"(a) : "l"(p));
    return a;
}

// ---------------- mma.sync m16n8k16 fp16 (fp32 accum) ----------------
__device__ __forceinline__ void mma16(float c[4], const uint32_t a[4], const uint32_t b[2]){
    asm volatile("mma.sync.aligned.m16n8k16.row.col.f32.f16.f16.f32 "
        "{%0,%1,%2,%3}, {%4,%5,%6,%7}, {%8,%9}, {%0,%1,%2,%3};"
        : "+f"(c[0]), "+f"(c[1]), "+f"(c[2]), "+f"(c[3])
        : "r"(a[0]), "r"(a[1]), "r"(a[2]), "r"(a[3]), "r"(b[0]), "r"(b[1]));
}

__device__ __forceinline__ void ldsm4(uint32_t r[4], uint32_t addr){
    asm volatile("ldmatrix.sync.aligned.m8n8.x4.shared.b16 {%0,%1,%2,%3}, [%4];"
        : "=r"(r[0]), "=r"(r[1]), "=r"(r[2]), "=r"(r[3]) : "r"(addr));
}

// ---------------------------------------------------------------------------
// prep: fused w_prep (blocks 0..345) + node_pre (blocks 346..6745)
// ---------------------------------------------------------------------------
__device__ __forceinline__ void packW(uint32_t* dst, const float* W, int N, int NT, int idx){
    const int ks  = idx / (NT*64);
    const int rem = idx - ks*(NT*64);
    const int nt  = rem >> 6;
    const int l2  = rem & 63;
    const int lane = l2 >> 1, r = l2 & 1;
    const int gg = lane >> 2, tg = lane & 3;
    const int k0 = ks*16 + 2*tg + 8*r;
    const int n  = nt*8 + gg;
    dst[idx] = h2pack(W[k0*N + n], W[(k0+1)*N + n]);
}

#define WPREP_BLOCKS 346   // 346*256 = 88576 exactly

__global__ void prep(const float* __restrict__ x,
                     const float* __restrict__ w0, const float* __restrict__ b0,
                     const float* __restrict__ w1, const float* __restrict__ w2,
                     const float* __restrict__ nw0, const float* __restrict__ nw1,
                     const float* __restrict__ nw2)
{
    const int t = threadIdx.x;
    if (blockIdx.x < WPREP_BLOCKS) {
        const int idx = blockIdx.x * 256 + t;
        if      (idx < 7680)        packW(g_w1h,  w1,  E1,  20, idx);
        else if (idx < 23040)       packW(g_w2h,  w2,  E2,  24, idx - 7680);
        else if (idx < 51712)       packW(g_nw0h, nw0, 256, 32, idx - 23040);
        else if (idx < 84480)       packW(g_nw1h, nw1, 256, 32, idx - 51712);
        else                        packW(g_nw2h, nw2, 32,  4,  idx - 84480);
        return;
    }
    __shared__ float sx[DD];
    const int node = blockIdx.x - WPREP_BLOCKS;
    if (t < E2) g_agg[node*E2 + t] = 0.f;
    if (t < DD) sx[t] = x[node*DD + t];
    __syncthreads();
    if (t < E2) {
        float acc = 0.f;
        if (t < E0) {
            const int c = t;
            #pragma unroll
            for (int k = 0; k < DD; k++) acc += sx[k] * w0[k*E0 + c];
            g_u[node*E0 + c] = acc + b0[c];
        } else {
            const int c = t - E0;
            #pragma unroll
            for (int k = 0; k < DD; k++) acc += sx[k] * w0[(DD+k)*E0 + c];
            g_v[node*E0 + c] = acc;
        }
    }
}

// ---------------------------------------------------------------------------
// edge_kernel: persistent, fp16 mma + ldmatrix, weights smem-resident.
// grid=304, block=256 (8 warps = 2m x 4n), smem = 28416 words = 113664 B
// region [0,5376): H0 (stride 52w) / H1 (stride 84w); sPart @4608 (768w)
// sW1 @5376 (7680w) | sW2 @13056 (15360w)
// (exact R7 champion config; CTA-level gating of second-segment reduce)
// ---------------------------------------------------------------------------
#define H0S 52
#define H1S 84
#define SPARTW 4608
#define SW1W 5376
#define SW2W 13056
#define EDGE_WORDS 28416
#define EDGE_SMEM_BYTES (EDGE_WORDS*4)

__global__ __launch_bounds__(256, 2)
void edge_kernel(const float* __restrict__ b1v, const float* __restrict__ b2v)
{
    extern __shared__ uint32_t smem_u[];
    uint32_t* region = smem_u;
    uint32_t* sW1 = smem_u + SW1W;
    uint32_t* sW2 = smem_u + SW2W;
    float*    sPart = (float*)(smem_u + SPARTW);   // [wm*2+seg][192]

    const int tid  = threadIdx.x;
    const int warp = tid >> 5;
    const int lane = tid & 31;
    const int g    = lane >> 2;
    const int tg   = lane & 3;
    const int wm   = warp >> 2;             // 0..1
    const int wn   = warp & 3;              // 0..3

    // ldmatrix per-lane address components
    const int lrow = lane & 15;
    const int lcol = (lane >> 4) * 4;
    const uint32_t regB = smem_to_u32(region);
    uint32_t a0H0 = regB + (((wm*32 +  0 + lrow)*H0S) + lcol)*4;
    uint32_t a1H0 = regB + (((wm*32 + 16 + lrow)*H0S) + lcol)*4;
    uint32_t a0H1 = regB + (((wm*32 +  0 + lrow)*H1S) + lcol)*4;
    uint32_t a1H1 = regB + (((wm*32 + 16 + lrow)*H1S) + lcol)*4;

    // hoist tile-invariant biases into registers
    float bb1[5][2], bb2[6][2];
    #pragma unroll
    for (int nt = 0; nt < 5; nt++) {
        const int col = wn*40 + nt*8 + 2*tg;
        bb1[nt][0] = __ldg(b1v + col);
        bb1[nt][1] = __ldg(b1v + col + 1);
    }
    #pragma unroll
    for (int nt = 0; nt < 6; nt++) {
        const int col = wn*48 + nt*8 + 2*tg;
        bb2[nt][0] = __ldg(b2v + col);
        bb2[nt][1] = __ldg(b2v + col + 1);
    }

    // ---- preload weights once ----
    {
        const uint32_t s1 = smem_to_u32(sW1);
        for (int i = tid; i < 1920; i += 256) CP_ASYNC16(s1 + i*16, (const void*)(g_w1h + i*4));
        const uint32_t s2 = smem_to_u32(sW2);
        for (int i = tid; i < 3840; i += 256) CP_ASYNC16(s2 + i*16, (const void*)(g_w2h + i*4));
        CP_COMMIT();
        CP_WAIT0();
    }
    __syncthreads();

    for (int tile = blockIdx.x; tile < NTILES; tile += GRID_E) {
        const int base = tile * TIL;

        // ---- build H0 = fp16(lrelu(u_i + v_j)) -> region [row][52w] ----
        {
            const int row = tid >> 2;
            const int kq  = tid & 3;
            const int R   = base + row;
            const int nu  = R / 100;
            const int nv  = (R / 10000) * 100 + (R - nu*100);
            const float4* up = (const float4*)(g_u + nu*E0) + kq*6;
            const float4* vp = (const float4*)(g_v + nv*E0) + kq*6;
            uint32_t* dst = region + row*H0S + kq*12;
            #pragma unroll
            for (int i = 0; i < 6; i++) {
                const float4 uu = up[i];
                const float4 vv = vp[i];
                uint2 w;
                w.x = h2pack(lrelu(uu.x + vv.x), lrelu(uu.y + vv.y));
                w.y = h2pack(lrelu(uu.z + vv.z), lrelu(uu.w + vv.w));
                *(uint2*)(dst + i*2) = w;
            }
        }
        __syncthreads();                               // (C)

        // ---- GEMM1: C1[64x160] = H0[64x96] @ W1 ----
        float c1[2][5][4];
        #pragma unroll
        for (int mt = 0; mt < 2; mt++)
            #pragma unroll
            for (int nt = 0; nt < 5; nt++)
                #pragma unroll
                for (int e = 0; e < 4; e++) c1[mt][nt][e] = 0.f;

        #pragma unroll
        for (int ks = 0; ks < 6; ks++) {
            uint32_t a0[4], a1[4];
            ldsm4(a0, a0H0 + ks*32);
            ldsm4(a1, a1H0 + ks*32);
            #pragma unroll
            for (int nt = 0; nt < 5; nt++) {
                uint32_t b[2];
                *(uint2*)b = *(const uint2*)&sW1[((ks*20 + wn*5 + nt)*32 + lane)*2];
                mma16(c1[0][nt], a0, b);
                mma16(c1[1][nt], a1, b);
            }
        }
        __syncthreads();                               // (D) H0 dead

        // ---- epilogue1: H1 = fp16(lrelu(C1 + b1)) -> region [row][84w] ----
        #pragma unroll
        for (int nt = 0; nt < 5; nt++) {
            const int col = wn*40 + nt*8 + 2*tg;
            #pragma unroll
            for (int mt = 0; mt < 2; mt++) {
                const int r0 = wm*32 + mt*16 + g;
                region[r0*H1S + (col>>1)]     = h2pack(lrelu(c1[mt][nt][0] + bb1[nt][0]), lrelu(c1[mt][nt][1] + bb1[nt][1]));
                region[(r0+8)*H1S + (col>>1)] = h2pack(lrelu(c1[mt][nt][2] + bb1[nt][0]), lrelu(c1[mt][nt][3] + bb1[nt][1]));
            }
        }
        __syncthreads();                               // (E)

        // ---- GEMM2: C2[64x192] = H1[64x160] @ W2 ----
        float c2[2][6][4];
        #pragma unroll
        for (int mt = 0; mt < 2; mt++)
            #pragma unroll
            for (int nt = 0; nt < 6; nt++)
                #pragma unroll
                for (int e = 0; e < 4; e++) c2[mt][nt][e] = 0.f;

        #pragma unroll
        for (int ks = 0; ks < 10; ks++) {
            uint32_t a0[4], a1[4];
            ldsm4(a0, a0H1 + ks*32);
            ldsm4(a1, a1H1 + ks*32);
            #pragma unroll
            for (int nt = 0; nt < 6; nt++) {
                uint32_t b[2];
                *(uint2*)b = *(const uint2*)&sW2[((ks*24 + wn*6 + nt)*32 + lane)*2];
                mma16(c2[0][nt], a0, b);
                mma16(c2[1][nt], a1, b);
            }
        }

        // ---- in-register segmented reduce (<=2 segments/tile) ----
        const int s0 = base / 100;
        int r1 = (s0 + 1)*100 - base;  if (r1 > TIL) r1 = TIL;
        const bool two = (r1 < TIL);                   // CTA-uniform

        float acc[2][12];
        #pragma unroll
        for (int s = 0; s < 2; s++)
            #pragma unroll
            for (int i = 0; i < 12; i++) acc[s][i] = 0.f;

        if (two) {
            #pragma unroll
            for (int nt = 0; nt < 6; nt++) {
                #pragma unroll
                for (int mt = 0; mt < 2; mt++) {
                    const int offA = wm*32 + mt*16 + g;
                    const int offB = offA + 8;
                    const int sA = (offA >= r1);
                    const int sB = (offB >= r1);
                    acc[sA][nt*2  ] += lrelu(c2[mt][nt][0] + bb2[nt][0]);
                    acc[sA][nt*2+1] += lrelu(c2[mt][nt][1] + bb2[nt][1]);
                    acc[sB][nt*2  ] += lrelu(c2[mt][nt][2] + bb2[nt][0]);
                    acc[sB][nt*2+1] += lrelu(c2[mt][nt][3] + bb2[nt][1]);
                }
            }
        } else {
            #pragma unroll
            for (int nt = 0; nt < 6; nt++) {
                #pragma unroll
                for (int mt = 0; mt < 2; mt++) {
                    acc[0][nt*2  ] += lrelu(c2[mt][nt][0] + bb2[nt][0]);
                    acc[0][nt*2+1] += lrelu(c2[mt][nt][1] + bb2[nt][1]);
                    acc[0][nt*2  ] += lrelu(c2[mt][nt][2] + bb2[nt][0]);
                    acc[0][nt*2+1] += lrelu(c2[mt][nt][3] + bb2[nt][1]);
                }
            }
        }
        #pragma unroll
        for (int off = 4; off < 32; off <<= 1)
            #pragma unroll
            for (int i = 0; i < 12; i++)
                acc[0][i] += __shfl_xor_sync(0xFFFFFFFFu, acc[0][i], off);
        if (two) {
            #pragma unroll
            for (int off = 4; off < 32; off <<= 1)
                #pragma unroll
                for (int i = 0; i < 12; i++)
                    acc[1][i] += __shfl_xor_sync(0xFFFFFFFFu, acc[1][i], off);
        }

        __syncthreads();                               // (A)

        if (g == 0) {
            #pragma unroll
            for (int nt = 0; nt < 6; nt++) {
                const int col = wn*48 + nt*8 + 2*tg;
                sPart[(wm*2 + 0)*192 + col    ] = acc[0][nt*2];
                sPart[(wm*2 + 0)*192 + col + 1] = acc[0][nt*2+1];
                if (two) {
                    sPart[(wm*2 + 1)*192 + col    ] = acc[1][nt*2];
                    sPart[(wm*2 + 1)*192 + col + 1] = acc[1][nt*2+1];
                }
            }
        }
        __syncthreads();                               // (B)

        if (tid < 192) {
            const float v0 = sPart[tid] + sPart[384 + tid];
            atomicAdd(&g_agg[s0*E2 + tid], v0);
            if (two) {
                const float v1 = sPart[192 + tid] + sPart[576 + tid];
                atomicAdd(&g_agg[(s0 + 1)*E2 + tid], v1);
            }
        }
        // next build writes [0,3328) only; sPart [4608,5376) untouched
    }
}

// ---------------------------------------------------------------------------
// node_mlp: fp16 mma + ldmatrix, 32 rows/CTA (two 16-row halves), grid=200,
// block=256. smem: bufA [32][132w] + bufB [32][132w]
// ---------------------------------------------------------------------------
#define NBS 132
#define NODE_SMEM_BYTES (2*32*NBS*4)

__global__ __launch_bounds__(256)
void node_mlp(const float* __restrict__ x,
              const float* __restrict__ b0,
              const float* __restrict__ b1,
              const float* __restrict__ b2,
              float* __restrict__ out)
{
    extern __shared__ uint32_t smem_u[];
    uint32_t* bufA = smem_u;
    uint32_t* bufB = smem_u + 32*NBS;

    const int tid  = threadIdx.x;
    const int warp = tid >> 5;
    const int lane = tid & 31;
    const int g    = lane >> 2;
    const int tg   = lane & 3;
    const int half = warp >> 2;
    const int wq   = warp & 3;
    const int base = blockIdx.x * 32;

    const int lrow = lane & 15;
    const int lcol = (lane >> 4) * 4;
    const uint32_t aA = smem_to_u32(bufA) + ((half*16 + lrow)*NBS + lcol)*4;
    const uint32_t aB = smem_to_u32(bufB) + ((half*16 + lrow)*NBS + lcol)*4;

    for (int i = tid; i < 32*112; i += 256) {
        const int row = i / 112;
        const int kw  = i - row*112;
        const int k   = kw*2;
        const int node = base + row;
        float v0, v1;
        if (k < E2) { v0 = g_agg[node*E2 + k]; v1 = g_agg[node*E2 + k + 1]; }
        else        { v0 = x[node*DD + (k - E2)]; v1 = x[node*DD + (k - E2) + 1]; }
        bufA[row*NBS + kw] = h2pack(v0, v1);
    }
    __syncthreads();

    for (int layer = 0; layer < 2; layer++) {
        const uint32_t aIn  = layer ? aB : aA;
        uint32_t* sOut      = layer ? bufA : bufB;
        const uint32_t* wpk = layer ? g_nw1h : g_nw0h;
        const float* bias   = layer ? b1 : b0;
        const int nks       = layer ? 16 : 14;

        float c[8][4];
        #pragma unroll
        for (int nt = 0; nt < 8; nt++)
            #pragma unroll
            for (int e = 0; e < 4; e++) c[nt][e] = 0.f;

        for (int ks = 0; ks < nks; ks++) {
            uint32_t a[4];
            ldsm4(a, aIn + ks*32);
            #pragma unroll
            for (int nt = 0; nt < 8; nt++) {
                uint32_t b[2];
                *(uint2*)b = *(const uint2*)&wpk[((ks*32 + wq*8 + nt)*32 + lane)*2];
                mma16(c[nt], a, b);
            }
        }
        __syncthreads();
        #pragma unroll
        for (int nt = 0; nt < 8; nt++) {
            const int col = wq*64 + nt*8 + 2*tg;
            const float ba = __ldg(bias + col);
            const float bb = __ldg(bias + col + 1);
            const int r0 = half*16 + g;
            sOut[r0*NBS + (col>>1)]     = h2pack(lrelu(c[nt][0] + ba), lrelu(c[nt][1] + bb));
            sOut[(r0+8)*NBS + (col>>1)] = h2pack(lrelu(c[nt][2] + ba), lrelu(c[nt][3] + bb));
        }
        __syncthreads();
    }

    {
        float c3[4] = {0.f, 0.f, 0.f, 0.f};
        for (int ks = 0; ks < 16; ks++) {
            uint32_t a[4];
            ldsm4(a, aA + ks*32);
            uint32_t b[2];
            *(uint2*)b = *(const uint2*)&g_nw2h[((ks*4 + wq)*32 + lane)*2];
            mma16(c3, a, b);
        }
        const int col = wq*8 + 2*tg;
        const float ba = __ldg(b2 + col);
        const float bb = __ldg(b2 + col + 1);
        float2 lo = {c3[0] + ba, c3[1] + bb};
        float2 hi = {c3[2] + ba, c3[3] + bb};
        const int r0 = base + half*16 + g;
        *(float2*)&out[r0*32 + col]       = lo;
        *(float2*)&out[(r0 + 8)*32 + col] = hi;
    }
}

// ---------------------------------------------------------------------------
extern "C" void kernel_launch(void* const* d_in, const int* in_sizes, int n_in,
                              void* d_out, int out_size)
{
    const float* x     = (const float*)d_in[0];
    const float* fe_w0 = (const float*)d_in[1];
    const float* fe_b0 = (const float*)d_in[2];
    const float* fe_w1 = (const float*)d_in[3];
    const float* fe_b1 = (const float*)d_in[4];
    const float* fe_w2 = (const float*)d_in[5];
    const float* fe_b2 = (const float*)d_in[6];
    const float* fn_w0 = (const float*)d_in[7];
    const float* fn_b0 = (const float*)d_in[8];
    const float* fn_w1 = (const float*)d_in[9];
    const float* fn_b1 = (const float*)d_in[10];
    const float* fn_w2 = (const float*)d_in[11];
    const float* fn_b2 = (const float*)d_in[12];
    float* out = (float*)d_out;

    cudaFuncSetAttribute(edge_kernel, cudaFuncAttributeMaxDynamicSharedMemorySize, EDGE_SMEM_BYTES);
    cudaFuncSetAttribute(node_mlp,    cudaFuncAttributeMaxDynamicSharedMemorySize, NODE_SMEM_BYTES);

    prep<<<WPREP_BLOCKS + NODES, 256>>>(x, fe_w0, fe_b0, fe_w1, fe_w2, fn_w0, fn_w1, fn_w2);
    edge_kernel<<<GRID_E, 256, EDGE_SMEM_BYTES>>>(fe_b1, fe_b2);
    node_mlp<<<NODES/32, 256, NODE_SMEM_BYTES>>>(x, fn_b0, fn_b1, fn_b2, out);
}

// round 16
// speedup vs baseline: 1.4120x; 1.0150x over previous
#include <cuda_runtime.h>
#include <cuda_fp16.h>
#include <cstdint>

// Problem constants
#define BB   64
#define NN   100
#define DD   32
#define E0   96
#define E1   160
#define E2   192
#define NODES (BB*NN)          // 6400
#define ROWS  (BB*NN*NN)       // 640000
#define TIL   64
#define NTILES (ROWS/TIL)      // 10000
#define GRID_E 304

// ---------------- scratch ----------------
__device__ __align__(16) float    g_u[NODES*E0];
__device__ __align__(16) float    g_v[NODES*E0];
__device__ __align__(16) float    g_agg[NODES*E2];
__device__ __align__(16) uint32_t g_w1h[6*20*64];    // 7680
__device__ __align__(16) uint32_t g_w2h[10*24*64];   // 15360
__device__ __align__(16) uint32_t g_nw0h[14*32*64];  // 28672
__device__ __align__(16) uint32_t g_nw1h[16*32*64];  // 32768
__device__ __align__(16) uint32_t g_nw2h[16*4*64];   // 4096

__device__ __forceinline__ float lrelu(float x){ return x > 0.f ? x : 0.2f*x; }

__device__ __forceinline__ uint32_t h2pack(float a, float b){
    __half2 h = __floats2half2_rn(a, b);
    return *(uint32_t*)&h;
}

// ---------------- cp.async ----------------
#define CP_ASYNC16(smem_u32, gptr) \
    asm volatile("cp.async.cg.shared.global [%0], [%1], 16;" :: "r"((uint32_t)(smem_u32)), "l"(gptr) : "memory")
#define CP_COMMIT() asm volatile("cp.async.commit_group;" ::: "memory")
#define CP_WAIT0()  asm volatile("cp.async.wait_group 0;" ::: "memory")

__device__ __forceinline__ uint32_t smem_to_u32(const void* p){
    uint32_t a;
    asm("{ .reg .u64 t; cvta.to.shared.u64 t, %1; cvt.u32.u64 %0, t; }" : "=r"(a) : "l"(p));
    return a;
}

// ---------------- mma.sync m16n8k16 fp16 (fp32 accum) ----------------
__device__ __forceinline__ void mma16(float c[4], const uint32_t a[4], const uint32_t b[2]){
    asm volatile("mma.sync.aligned.m16n8k16.row.col.f32.f16.f16.f32 "
        "{%0,%1,%2,%3}, {%4,%5,%6,%7}, {%8,%9}, {%0,%1,%2,%3};"
        : "+f"(c[0]), "+f"(c[1]), "+f"(c[2]), "+f"(c[3])
        : "r"(a[0]), "r"(a[1]), "r"(a[2]), "r"(a[3]), "r"(b[0]), "r"(b[1]));
}

__device__ __forceinline__ void ldsm4(uint32_t r[4], uint32_t addr){
    asm volatile("ldmatrix.sync.aligned.m8n8.x4.shared.b16 {%0,%1,%2,%3}, [%4];"
        : "=r"(r[0]), "=r"(r[1]), "=r"(r[2]), "=r"(r[3]) : "r"(addr));
}

// ---------------------------------------------------------------------------
// prep: fused w_prep (blocks 0..345) + node_pre (blocks 346..545, 32 nodes ea)
// node_pre stages fe_w0 + b0 + 32 x-rows in smem: w0 L2 traffic 157MB -> 4.8MB
// ---------------------------------------------------------------------------
__device__ __forceinline__ void packW(uint32_t* dst, const float* W, int N, int NT, int idx){
    const int ks  = idx / (NT*64);
    const int rem = idx - ks*(NT*64);
    const int nt  = rem >> 6;
    const int l2  = rem & 63;
    const int lane = l2 >> 1, r = l2 & 1;
    const int gg = lane >> 2, tg = lane & 3;
    const int k0 = ks*16 + 2*tg + 8*r;
    const int n  = nt*8 + gg;
    dst[idx] = h2pack(W[k0*N + n], W[(k0+1)*N + n]);
}

#define WPREP_BLOCKS 346   // 346*256 = 88576 exactly
#define NODE_BLOCKS  200   // 32 nodes each

__global__ void prep(const float* __restrict__ x,
                     const float* __restrict__ w0, const float* __restrict__ b0,
                     const float* __restrict__ w1, const float* __restrict__ w2,
                     const float* __restrict__ nw0, const float* __restrict__ nw1,
                     const float* __restrict__ nw2)
{
    const int t = threadIdx.x;
    if (blockIdx.x < WPREP_BLOCKS) {
        const int idx = blockIdx.x * 256 + t;
        if      (idx < 7680)        packW(g_w1h,  w1,  E1,  20, idx);
        else if (idx < 23040)       packW(g_w2h,  w2,  E2,  24, idx - 7680);
        else if (idx < 51712)       packW(g_nw0h, nw0, 256, 32, idx - 23040);
        else if (idx < 84480)       packW(g_nw1h, nw1, 256, 32, idx - 51712);
        else                        packW(g_nw2h, nw2, 32,  4,  idx - 84480);
        return;
    }

    // node_pre: 32 nodes per block, w0/b0/x staged in smem
    __shared__ float sw0[64*E0];    // 6144 floats = 24 KB
    __shared__ float sb0[E0];
    __shared__ float sx[32*DD];     // 1024 floats

    const int blk   = blockIdx.x - WPREP_BLOCKS;
    const int node0 = blk * 32;

    for (int i = t; i < 64*E0; i += 256) sw0[i] = w0[i];
    if (t < E0) sb0[t] = b0[t];
    for (int i = t; i < 32*DD; i += 256) sx[i] = x[node0*DD + i];
    // zero g_agg for these 32 nodes (32*192 = 6144 floats)
    for (int i = t; i < 32*E2; i += 256) g_agg[node0*E2 + i] = 0.f;
    __syncthreads();

    // 32 nodes x 192 cols = 6144 dots; idx = n*192 + c (coalesced in c)
    for (int idx = t; idx < 32*E2; idx += 256) {
        const int n = idx / E2;
        const int c = idx - n*E2;
        const float* xr = sx + n*DD;
        float acc = 0.f;
        if (c < E0) {
            #pragma unroll
            for (int k = 0; k < DD; k++) acc += xr[k] * sw0[k*E0 + c];
            g_u[(node0 + n)*E0 + c] = acc + sb0[c];
        } else {
            const int cc = c - E0;
            #pragma unroll
            for (int k = 0; k < DD; k++) acc += xr[k] * sw0[(DD+k)*E0 + cc];
            g_v[(node0 + n)*E0 + cc] = acc;
        }
    }
}

// ---------------------------------------------------------------------------
// edge_kernel: persistent, fp16 mma + ldmatrix, weights smem-resident.
// grid=304, block=256 (8 warps = 2m x 4n), smem = 28416 words = 113664 B
// region [0,5376): H0 (stride 52w) / H1 (stride 84w); sPart @4608 (768w)
// sW1 @5376 (7680w) | sW2 @13056 (15360w)
// (champion config; CTA-level gating of second-segment reduce)
// ---------------------------------------------------------------------------
#define H0S 52
#define H1S 84
#define SPARTW 4608
#define SW1W 5376
#define SW2W 13056
#define EDGE_WORDS 28416
#define EDGE_SMEM_BYTES (EDGE_WORDS*4)

__global__ __launch_bounds__(256, 2)
void edge_kernel(const float* __restrict__ b1v, const float* __restrict__ b2v)
{
    extern __shared__ uint32_t smem_u[];
    uint32_t* region = smem_u;
    uint32_t* sW1 = smem_u + SW1W;
    uint32_t* sW2 = smem_u + SW2W;
    float*    sPart = (float*)(smem_u + SPARTW);   // [wm*2+seg][192]

    const int tid  = threadIdx.x;
    const int warp = tid >> 5;
    const int lane = tid & 31;
    const int g    = lane >> 2;
    const int tg   = lane & 3;
    const int wm   = warp >> 2;             // 0..1
    const int wn   = warp & 3;              // 0..3

    // ldmatrix per-lane address components
    const int lrow = lane & 15;
    const int lcol = (lane >> 4) * 4;
    const uint32_t regB = smem_to_u32(region);
    uint32_t a0H0 = regB + (((wm*32 +  0 + lrow)*H0S) + lcol)*4;
    uint32_t a1H0 = regB + (((wm*32 + 16 + lrow)*H0S) + lcol)*4;
    uint32_t a0H1 = regB + (((wm*32 +  0 + lrow)*H1S) + lcol)*4;
    uint32_t a1H1 = regB + (((wm*32 + 16 + lrow)*H1S) + lcol)*4;

    // hoist tile-invariant biases into registers
    float bb1[5][2], bb2[6][2];
    #pragma unroll
    for (int nt = 0; nt < 5; nt++) {
        const int col = wn*40 + nt*8 + 2*tg;
        bb1[nt][0] = __ldg(b1v + col);
        bb1[nt][1] = __ldg(b1v + col + 1);
    }
    #pragma unroll
    for (int nt = 0; nt < 6; nt++) {
        const int col = wn*48 + nt*8 + 2*tg;
        bb2[nt][0] = __ldg(b2v + col);
        bb2[nt][1] = __ldg(b2v + col + 1);
    }

    // ---- preload weights once ----
    {
        const uint32_t s1 = smem_to_u32(sW1);
        for (int i = tid; i < 1920; i += 256) CP_ASYNC16(s1 + i*16, (const void*)(g_w1h + i*4));
        const uint32_t s2 = smem_to_u32(sW2);
        for (int i = tid; i < 3840; i += 256) CP_ASYNC16(s2 + i*16, (const void*)(g_w2h + i*4));
        CP_COMMIT();
        CP_WAIT0();
    }
    __syncthreads();

    for (int tile = blockIdx.x; tile < NTILES; tile += GRID_E) {
        const int base = tile * TIL;

        // ---- build H0 = fp16(lrelu(u_i + v_j)) -> region [row][52w] ----
        {
            const int row = tid >> 2;
            const int kq  = tid & 3;
            const int R   = base + row;
            const int nu  = R / 100;
            const int nv  = (R / 10000) * 100 + (R - nu*100);
            const float4* up = (const float4*)(g_u + nu*E0) + kq*6;
            const float4* vp = (const float4*)(g_v + nv*E0) + kq*6;
            uint32_t* dst = region + row*H0S + kq*12;
            #pragma unroll
            for (int i = 0; i < 6; i++) {
                const float4 uu = up[i];
                const float4 vv = vp[i];
                uint2 w;
                w.x = h2pack(lrelu(uu.x + vv.x), lrelu(uu.y + vv.y));
                w.y = h2pack(lrelu(uu.z + vv.z), lrelu(uu.w + vv.w));
                *(uint2*)(dst + i*2) = w;
            }
        }
        __syncthreads();                               // (C)

        // ---- GEMM1: C1[64x160] = H0[64x96] @ W1 ----
        float c1[2][5][4];
        #pragma unroll
        for (int mt = 0; mt < 2; mt++)
            #pragma unroll
            for (int nt = 0; nt < 5; nt++)
                #pragma unroll
                for (int e = 0; e < 4; e++) c1[mt][nt][e] = 0.f;

        #pragma unroll
        for (int ks = 0; ks < 6; ks++) {
            uint32_t a0[4], a1[4];
            ldsm4(a0, a0H0 + ks*32);
            ldsm4(a1, a1H0 + ks*32);
            #pragma unroll
            for (int nt = 0; nt < 5; nt++) {
                uint32_t b[2];
                *(uint2*)b = *(const uint2*)&sW1[((ks*20 + wn*5 + nt)*32 + lane)*2];
                mma16(c1[0][nt], a0, b);
                mma16(c1[1][nt], a1, b);
            }
        }
        __syncthreads();                               // (D) H0 dead

        // ---- epilogue1: H1 = fp16(lrelu(C1 + b1)) -> region [row][84w] ----
        #pragma unroll
        for (int nt = 0; nt < 5; nt++) {
            const int col = wn*40 + nt*8 + 2*tg;
            #pragma unroll
            for (int mt = 0; mt < 2; mt++) {
                const int r0 = wm*32 + mt*16 + g;
                region[r0*H1S + (col>>1)]     = h2pack(lrelu(c1[mt][nt][0] + bb1[nt][0]), lrelu(c1[mt][nt][1] + bb1[nt][1]));
                region[(r0+8)*H1S + (col>>1)] = h2pack(lrelu(c1[mt][nt][2] + bb1[nt][0]), lrelu(c1[mt][nt][3] + bb1[nt][1]));
            }
        }
        __syncthreads();                               // (E)

        // ---- GEMM2: C2[64x192] = H1[64x160] @ W2 ----
        float c2[2][6][4];
        #pragma unroll
        for (int mt = 0; mt < 2; mt++)
            #pragma unroll
            for (int nt = 0; nt < 6; nt++)
                #pragma unroll
                for (int e = 0; e < 4; e++) c2[mt][nt][e] = 0.f;

        #pragma unroll
        for (int ks = 0; ks < 10; ks++) {
            uint32_t a0[4], a1[4];
            ldsm4(a0, a0H1 + ks*32);
            ldsm4(a1, a1H1 + ks*32);
            #pragma unroll
            for (int nt = 0; nt < 6; nt++) {
                uint32_t b[2];
                *(uint2*)b = *(const uint2*)&sW2[((ks*24 + wn*6 + nt)*32 + lane)*2];
                mma16(c2[0][nt], a0, b);
                mma16(c2[1][nt], a1, b);
            }
        }

        // ---- in-register segmented reduce (<=2 segments/tile) ----
        const int s0 = base / 100;
        int r1 = (s0 + 1)*100 - base;  if (r1 > TIL) r1 = TIL;
        const bool two = (r1 < TIL);                   // CTA-uniform

        float acc[2][12];
        #pragma unroll
        for (int s = 0; s < 2; s++)
            #pragma unroll
            for (int i = 0; i < 12; i++) acc[s][i] = 0.f;

        if (two) {
            #pragma unroll
            for (int nt = 0; nt < 6; nt++) {
                #pragma unroll
                for (int mt = 0; mt < 2; mt++) {
                    const int offA = wm*32 + mt*16 + g;
                    const int offB = offA + 8;
                    const int sA = (offA >= r1);
                    const int sB = (offB >= r1);
                    acc[sA][nt*2  ] += lrelu(c2[mt][nt][0] + bb2[nt][0]);
                    acc[sA][nt*2+1] += lrelu(c2[mt][nt][1] + bb2[nt][1]);
                    acc[sB][nt*2  ] += lrelu(c2[mt][nt][2] + bb2[nt][0]);
                    acc[sB][nt*2+1] += lrelu(c2[mt][nt][3] + bb2[nt][1]);
                }
            }
        } else {
            #pragma unroll
            for (int nt = 0; nt < 6; nt++) {
                #pragma unroll
                for (int mt = 0; mt < 2; mt++) {
                    acc[0][nt*2  ] += lrelu(c2[mt][nt][0] + bb2[nt][0]);
                    acc[0][nt*2+1] += lrelu(c2[mt][nt][1] + bb2[nt][1]);
                    acc[0][nt*2  ] += lrelu(c2[mt][nt][2] + bb2[nt][0]);
                    acc[0][nt*2+1] += lrelu(c2[mt][nt][3] + bb2[nt][1]);
                }
            }
        }
        #pragma unroll
        for (int off = 4; off < 32; off <<= 1)
            #pragma unroll
            for (int i = 0; i < 12; i++)
                acc[0][i] += __shfl_xor_sync(0xFFFFFFFFu, acc[0][i], off);
        if (two) {
            #pragma unroll
            for (int off = 4; off < 32; off <<= 1)
                #pragma unroll
                for (int i = 0; i < 12; i++)
                    acc[1][i] += __shfl_xor_sync(0xFFFFFFFFu, acc[1][i], off);
        }

        __syncthreads();                               // (A)

        if (g == 0) {
            #pragma unroll
            for (int nt = 0; nt < 6; nt++) {
                const int col = wn*48 + nt*8 + 2*tg;
                sPart[(wm*2 + 0)*192 + col    ] = acc[0][nt*2];
                sPart[(wm*2 + 0)*192 + col + 1] = acc[0][nt*2+1];
                if (two) {
                    sPart[(wm*2 + 1)*192 + col    ] = acc[1][nt*2];
                    sPart[(wm*2 + 1)*192 + col + 1] = acc[1][nt*2+1];
                }
            }
        }
        __syncthreads();                               // (B)

        if (tid < 192) {
            const float v0 = sPart[tid] + sPart[384 + tid];
            atomicAdd(&g_agg[s0*E2 + tid], v0);
            if (two) {
                const float v1 = sPart[192 + tid] + sPart[576 + tid];
                atomicAdd(&g_agg[(s0 + 1)*E2 + tid], v1);
            }
        }
        // next build writes [0,3328) only; sPart [4608,5376) untouched
    }
}

// ---------------------------------------------------------------------------
// node_mlp: fp16 mma + ldmatrix, 32 rows/CTA (two 16-row halves), grid=200,
// block=256. smem: bufA [32][132w] + bufB [32][132w]
// ---------------------------------------------------------------------------
#define NBS 132
#define NODE_SMEM_BYTES (2*32*NBS*4)

__global__ __launch_bounds__(256)
void node_mlp(const float* __restrict__ x,
              const float* __restrict__ b0,
              const float* __restrict__ b1,
              const float* __restrict__ b2,
              float* __restrict__ out)
{
    extern __shared__ uint32_t smem_u[];
    uint32_t* bufA = smem_u;
    uint32_t* bufB = smem_u + 32*NBS;

    const int tid  = threadIdx.x;
    const int warp = tid >> 5;
    const int lane = tid & 31;
    const int g    = lane >> 2;
    const int tg   = lane & 3;
    const int half = warp >> 2;
    const int wq   = warp & 3;
    const int base = blockIdx.x * 32;

    const int lrow = lane & 15;
    const int lcol = (lane >> 4) * 4;
    const uint32_t aA = smem_to_u32(bufA) + ((half*16 + lrow)*NBS + lcol)*4;
    const uint32_t aB = smem_to_u32(bufB) + ((half*16 + lrow)*NBS + lcol)*4;

    for (int i = tid; i < 32*112; i += 256) {
        const int row = i / 112;
        const int kw  = i - row*112;
        const int k   = kw*2;
        const int node = base + row;
        float v0, v1;
        if (k < E2) { v0 = g_agg[node*E2 + k]; v1 = g_agg[node*E2 + k + 1]; }
        else        { v0 = x[node*DD + (k - E2)]; v1 = x[node*DD + (k - E2) + 1]; }
        bufA[row*NBS + kw] = h2pack(v0, v1);
    }
    __syncthreads();

    for (int layer = 0; layer < 2; layer++) {
        const uint32_t aIn  = layer ? aB : aA;
        uint32_t* sOut      = layer ? bufA : bufB;
        const uint32_t* wpk = layer ? g_nw1h : g_nw0h;
        const float* bias   = layer ? b1 : b0;
        const int nks       = layer ? 16 : 14;

        float c[8][4];
        #pragma unroll
        for (int nt = 0; nt < 8; nt++)
            #pragma unroll
            for (int e = 0; e < 4; e++) c[nt][e] = 0.f;

        for (int ks = 0; ks < nks; ks++) {
            uint32_t a[4];
            ldsm4(a, aIn + ks*32);
            #pragma unroll
            for (int nt = 0; nt < 8; nt++) {
                uint32_t b[2];
                *(uint2*)b = *(const uint2*)&wpk[((ks*32 + wq*8 + nt)*32 + lane)*2];
                mma16(c[nt], a, b);
            }
        }
        __syncthreads();
        #pragma unroll
        for (int nt = 0; nt < 8; nt++) {
            const int col = wq*64 + nt*8 + 2*tg;
            const float ba = __ldg(bias + col);
            const float bb = __ldg(bias + col + 1);
            const int r0 = half*16 + g;
            sOut[r0*NBS + (col>>1)]     = h2pack(lrelu(c[nt][0] + ba), lrelu(c[nt][1] + bb));
            sOut[(r0+8)*NBS + (col>>1)] = h2pack(lrelu(c[nt][2] + ba), lrelu(c[nt][3] + bb));
        }
        __syncthreads();
    }

    {
        float c3[4] = {0.f, 0.f, 0.f, 0.f};
        for (int ks = 0; ks < 16; ks++) {
            uint32_t a[4];
            ldsm4(a, aA + ks*32);
            uint32_t b[2];
            *(uint2*)b = *(const uint2*)&g_nw2h[((ks*4 + wq)*32 + lane)*2];
            mma16(c3, a, b);
        }
        const int col = wq*8 + 2*tg;
        const float ba = __ldg(b2 + col);
        const float bb = __ldg(b2 + col + 1);
        float2 lo = {c3[0] + ba, c3[1] + bb};
        float2 hi = {c3[2] + ba, c3[3] + bb};
        const int r0 = base + half*16 + g;
        *(float2*)&out[r0*32 + col]       = lo;
        *(float2*)&out[(r0 + 8)*32 + col] = hi;
    }
}

// ---------------------------------------------------------------------------
extern "C" void kernel_launch(void* const* d_in, const int* in_sizes, int n_in,
                              void* d_out, int out_size)
{
    const float* x     = (const float*)d_in[0];
    const float* fe_w0 = (const float*)d_in[1];
    const float* fe_b0 = (const float*)d_in[2];
    const float* fe_w1 = (const float*)d_in[3];
    const float* fe_b1 = (const float*)d_in[4];
    const float* fe_w2 = (const float*)d_in[5];
    const float* fe_b2 = (const float*)d_in[6];
    const float* fn_w0 = (const float*)d_in[7];
    const float* fn_b0 = (const float*)d_in[8];
    const float* fn_w1 = (const float*)d_in[9];
    const float* fn_b1 = (const float*)d_in[10];
    const float* fn_w2 = (const float*)d_in[11];
    const float* fn_b2 = (const float*)d_in[12];
    float* out = (float*)d_out;

    cudaFuncSetAttribute(edge_kernel, cudaFuncAttributeMaxDynamicSharedMemorySize, EDGE_SMEM_BYTES);
    cudaFuncSetAttribute(node_mlp,    cudaFuncAttributeMaxDynamicSharedMemorySize, NODE_SMEM_BYTES);

    prep<<<WPREP_BLOCKS + NODE_BLOCKS, 256>>>(x, fe_w0, fe_b0, fe_w1, fe_w2, fn_w0, fn_w1, fn_w2);
    edge_kernel<<<GRID_E, 256, EDGE_SMEM_BYTES>>>(fe_b1, fe_b2);
    node_mlp<<<NODES/32, 256, NODE_SMEM_BYTES>>>(x, fn_b0, fn_b1, fn_b2, out);
}